// round 1
// baseline (speedup 1.0000x reference)
#include <cuda_runtime.h>
#include <cuda_bf16.h>

// Problem constants (match reference_code)
#define NN 262144
#define KK 1024
#define DD 256
#define DECAY 0.99f
#define ONE_MINUS_DECAY 0.01f
#define EPS 1e-5f

// Scratch (device globals; no allocation allowed in kernel_launch)
__device__ int   g_counts[KK];
__device__ int   g_offsets[KK + 1];
__device__ int   g_cursor[KK];
__device__ int   g_order[NN];
__device__ float g_inv_smoothed[KK];

// ---------------------------------------------------------------------------
// Kernel 0: zero the per-launch scratch (graph replays reuse globals)
// ---------------------------------------------------------------------------
__global__ void k_zero() {
    int t = threadIdx.x;
    if (t < KK) g_counts[t] = 0;
}

// ---------------------------------------------------------------------------
// Kernel 1: histogram of indices, privatized in shared memory
// ---------------------------------------------------------------------------
__global__ void k_hist(const int* __restrict__ idx) {
    __shared__ int h[KK];
    for (int i = threadIdx.x; i < KK; i += blockDim.x) h[i] = 0;
    __syncthreads();
    for (int i = blockIdx.x * blockDim.x + threadIdx.x; i < NN;
         i += gridDim.x * blockDim.x) {
        atomicAdd(&h[idx[i]], 1);
    }
    __syncthreads();
    for (int i = threadIdx.x; i < KK; i += blockDim.x) {
        int v = h[i];
        if (v) atomicAdd(&g_counts[i], v);
    }
}

// ---------------------------------------------------------------------------
// Kernel 2: single block, 1024 threads.
//  - exclusive scan of counts -> offsets, cursor
//  - new_cs = cs*DECAY + (1-DECAY)*counts  -> out_cs
//  - n = sum(new_cs); inv_smoothed[k] = (n + K*EPS) / ((new_cs[k]+EPS) * n)
// ---------------------------------------------------------------------------
__global__ void k_scan_cs(const float* __restrict__ cluster_size,
                          float* __restrict__ out_cs) {
    int t = threadIdx.x;           // 0..1023
    int lane = t & 31, warp = t >> 5;

    int c = g_counts[t];

    // inclusive warp scan
    int incl = c;
    #pragma unroll
    for (int o = 1; o < 32; o <<= 1) {
        int x = __shfl_up_sync(0xffffffffu, incl, o);
        if (lane >= o) incl += x;
    }
    __shared__ int wsum[32];
    if (lane == 31) wsum[warp] = incl;
    __syncthreads();
    if (warp == 0) {
        int s = wsum[lane];
        int si = s;
        #pragma unroll
        for (int o = 1; o < 32; o <<= 1) {
            int x = __shfl_up_sync(0xffffffffu, si, o);
            if (lane >= o) si += x;
        }
        wsum[lane] = si - s;       // exclusive warp offsets
    }
    __syncthreads();
    int excl = incl - c + wsum[warp];

    g_offsets[t] = excl;
    g_cursor[t]  = excl;
    if (t == KK - 1) g_offsets[KK] = excl + c;

    float ncs = cluster_size[t] * DECAY + ONE_MINUS_DECAY * (float)c;
    out_cs[t] = ncs;

    // block reduction for n = sum(new_cs)
    float v = ncs;
    #pragma unroll
    for (int o = 16; o > 0; o >>= 1)
        v += __shfl_down_sync(0xffffffffu, v, o);
    __shared__ float wred[32];
    if (lane == 0) wred[warp] = v;
    __syncthreads();
    __shared__ float n_sh;
    if (warp == 0) {
        float s = wred[lane];
        #pragma unroll
        for (int o = 16; o > 0; o >>= 1)
            s += __shfl_down_sync(0xffffffffu, s, o);
        if (lane == 0) n_sh = s;
    }
    __syncthreads();
    float n = n_sh;

    // smoothed = (ncs + EPS) / (n + K*EPS) * n ; store reciprocal
    float smoothed = (ncs + EPS) / (n + (float)KK * EPS) * n;
    g_inv_smoothed[t] = 1.0f / smoothed;
}

// ---------------------------------------------------------------------------
// Kernel 3: scatter row ids into code-sorted order
// ---------------------------------------------------------------------------
__global__ void k_scatter(const int* __restrict__ idx) {
    int i = blockIdx.x * blockDim.x + threadIdx.x;
    if (i < NN) {
        int k = idx[i];
        int pos = atomicAdd(&g_cursor[k], 1);
        g_order[pos] = i;
    }
}

// ---------------------------------------------------------------------------
// Kernel 4: per-code gather-reduce + fused EMA epilogue.
// One CTA per code; thread d owns column d. Reads each encoding row once,
// coalesced. No float atomics anywhere.
// ---------------------------------------------------------------------------
__global__ void __launch_bounds__(DD) k_reduce(
    const float* __restrict__ enc,
    const float* __restrict__ embed_avg,
    float* __restrict__ out_ea,
    float* __restrict__ out_norm) {
    int k = blockIdx.x;
    int d = threadIdx.x;

    int start = g_offsets[k];
    int end   = g_offsets[k + 1];

    float a0 = 0.f, a1 = 0.f, a2 = 0.f, a3 = 0.f;

    int j = start;
    for (; j + 8 <= end; j += 8) {
        int r0 = g_order[j + 0];
        int r1 = g_order[j + 1];
        int r2 = g_order[j + 2];
        int r3 = g_order[j + 3];
        int r4 = g_order[j + 4];
        int r5 = g_order[j + 5];
        int r6 = g_order[j + 6];
        int r7 = g_order[j + 7];
        float v0 = __ldg(enc + (size_t)r0 * DD + d);
        float v1 = __ldg(enc + (size_t)r1 * DD + d);
        float v2 = __ldg(enc + (size_t)r2 * DD + d);
        float v3 = __ldg(enc + (size_t)r3 * DD + d);
        float v4 = __ldg(enc + (size_t)r4 * DD + d);
        float v5 = __ldg(enc + (size_t)r5 * DD + d);
        float v6 = __ldg(enc + (size_t)r6 * DD + d);
        float v7 = __ldg(enc + (size_t)r7 * DD + d);
        a0 += v0 + v4;
        a1 += v1 + v5;
        a2 += v2 + v6;
        a3 += v3 + v7;
    }
    for (; j < end; ++j) {
        int r = g_order[j];
        a0 += __ldg(enc + (size_t)r * DD + d);
    }
    float acc = (a0 + a1) + (a2 + a3);

    size_t o = (size_t)k * DD + d;
    float nea = embed_avg[o] * DECAY + ONE_MINUS_DECAY * acc;
    out_ea[o]   = nea;
    out_norm[o] = nea * g_inv_smoothed[k];
}

// ---------------------------------------------------------------------------
// Launch
// Inputs (metadata order): indices[int32 N], encodings[f32 N*D],
//                          cluster_size[f32 K], embed_avg[f32 K*D]
// Output: concat(new_cs[K], new_ea[K*D], embed_normalized[K*D]) = 525312 f32
// ---------------------------------------------------------------------------
extern "C" void kernel_launch(void* const* d_in, const int* in_sizes, int n_in,
                              void* d_out, int out_size) {
    const int*   indices      = (const int*)d_in[0];
    const float* encodings    = (const float*)d_in[1];
    const float* cluster_size = (const float*)d_in[2];
    const float* embed_avg    = (const float*)d_in[3];

    float* out_cs   = (float*)d_out;                 // [K]
    float* out_ea   = out_cs + KK;                   // [K, D]
    float* out_norm = out_ea + (size_t)KK * DD;      // [K, D]

    k_zero<<<1, KK>>>();
    k_hist<<<256, 256>>>(indices);
    k_scan_cs<<<1, KK>>>(cluster_size, out_cs);
    k_scatter<<<NN / 256, 256>>>(indices);
    k_reduce<<<KK, DD>>>(encodings, embed_avg, out_ea, out_norm);
}

// round 2
// speedup vs baseline: 1.2616x; 1.2616x over previous
#include <cuda_runtime.h>
#include <cuda_bf16.h>

// Problem constants (match reference_code)
#define NN 262144
#define KK 1024
#define DD 256
#define NB 256               // number of hist/scatter blocks (NN / 1024)
#define CHUNK 1024           // indices per block
#define DECAY 0.99f
#define ONE_MINUS_DECAY 0.01f
#define EPS 1e-5f

// Scratch (device globals; no allocation allowed)
__device__ int   g_bh[KK * NB];       // per-code-per-block hist -> exclusive prefix
__device__ int   g_ktotal[KK];        // per-code total count
__device__ int   g_offsets[KK + 1];   // exclusive scan over codes
__device__ int   g_order[NN];         // row ids grouped by code
__device__ float g_inv_smoothed[KK];

// ---------------------------------------------------------------------------
// Kernel 1: per-block histogram (smem atomics only), write g_bh[k*NB + b]
// ---------------------------------------------------------------------------
__global__ void __launch_bounds__(CHUNK) k_blockhist(const int* __restrict__ idx) {
    __shared__ int h[KK];
    int t = threadIdx.x;
    int b = blockIdx.x;
    h[t] = 0;
    __syncthreads();
    int k = idx[b * CHUNK + t];
    atomicAdd(&h[k], 1);
    __syncthreads();
    g_bh[t * NB + b] = h[t];
}

// ---------------------------------------------------------------------------
// Kernel 2a: per-code exclusive scan over the 256 block counts (contiguous).
// Writes prefix in place, per-code total to g_ktotal.
// ---------------------------------------------------------------------------
__global__ void __launch_bounds__(NB) k_scan_blocks() {
    int k = blockIdx.x;
    int t = threadIdx.x;            // 0..255
    int lane = t & 31, warp = t >> 5;

    int c = g_bh[k * NB + t];
    int incl = c;
    #pragma unroll
    for (int o = 1; o < 32; o <<= 1) {
        int x = __shfl_up_sync(0xffffffffu, incl, o);
        if (lane >= o) incl += x;
    }
    __shared__ int wsum[8];
    if (lane == 31) wsum[warp] = incl;
    __syncthreads();
    if (warp == 0 && lane < 8) {
        int s = wsum[lane];
        int si = s;
        #pragma unroll
        for (int o = 1; o < 8; o <<= 1) {
            int x = __shfl_up_sync(0xffu, si, o);
            if (lane >= o) si += x;
        }
        wsum[lane] = si - s;
    }
    __syncthreads();
    int excl = incl - c + wsum[warp];
    g_bh[k * NB + t] = excl;
    if (t == NB - 1) g_ktotal[k] = excl + c;
}

// ---------------------------------------------------------------------------
// Kernel 2b: single block, 1024 threads.
//  - exclusive scan of g_ktotal -> g_offsets
//  - new_cs = cs*DECAY + (1-DECAY)*counts  -> out_cs
//  - n = sum(new_cs); inv_smoothed[k] = 1 / ((new_cs[k]+EPS)/(n+K*EPS)*n)
// ---------------------------------------------------------------------------
__global__ void __launch_bounds__(KK) k_scan_cs(const float* __restrict__ cluster_size,
                                                float* __restrict__ out_cs) {
    int t = threadIdx.x;
    int lane = t & 31, warp = t >> 5;

    int c = g_ktotal[t];

    int incl = c;
    #pragma unroll
    for (int o = 1; o < 32; o <<= 1) {
        int x = __shfl_up_sync(0xffffffffu, incl, o);
        if (lane >= o) incl += x;
    }
    __shared__ int wsum[32];
    if (lane == 31) wsum[warp] = incl;
    __syncthreads();
    if (warp == 0) {
        int s = wsum[lane];
        int si = s;
        #pragma unroll
        for (int o = 1; o < 32; o <<= 1) {
            int x = __shfl_up_sync(0xffffffffu, si, o);
            if (lane >= o) si += x;
        }
        wsum[lane] = si - s;
    }
    __syncthreads();
    int excl = incl - c + wsum[warp];

    g_offsets[t] = excl;
    if (t == KK - 1) g_offsets[KK] = excl + c;

    float ncs = cluster_size[t] * DECAY + ONE_MINUS_DECAY * (float)c;
    out_cs[t] = ncs;

    float v = ncs;
    #pragma unroll
    for (int o = 16; o > 0; o >>= 1)
        v += __shfl_down_sync(0xffffffffu, v, o);
    __shared__ float wred[32];
    if (lane == 0) wred[warp] = v;
    __syncthreads();
    __shared__ float n_sh;
    if (warp == 0) {
        float s = wred[lane];
        #pragma unroll
        for (int o = 16; o > 0; o >>= 1)
            s += __shfl_down_sync(0xffffffffu, s, o);
        if (lane == 0) n_sh = s;
    }
    __syncthreads();
    float n = n_sh;

    float smoothed = (ncs + EPS) / (n + (float)KK * EPS) * n;
    g_inv_smoothed[t] = 1.0f / smoothed;
}

// ---------------------------------------------------------------------------
// Kernel 3: scatter — rank via smem atomics; base from two-level prefix.
// No global atomics.
// ---------------------------------------------------------------------------
__global__ void __launch_bounds__(CHUNK) k_scatter(const int* __restrict__ idx) {
    __shared__ int cur[KK];
    int t = threadIdx.x;
    int b = blockIdx.x;
    cur[t] = 0;
    __syncthreads();
    int i = b * CHUNK + t;
    int k = idx[i];
    int r = atomicAdd(&cur[k], 1);
    int base = g_offsets[k] + g_bh[k * NB + b];
    g_order[base + r] = i;
}

// ---------------------------------------------------------------------------
// Kernel 4: per-code gather-reduce (float4) + fused EMA epilogue.
// 64 lanes cover a row as float4; 4 row-phases per CTA; smem cross-phase
// reduction. Every encoding row read exactly once, coalesced.
// ---------------------------------------------------------------------------
__global__ void __launch_bounds__(256) k_reduce(
    const float4* __restrict__ enc,        // [N, 64] float4
    const float4* __restrict__ embed_avg,  // [K, 64] float4
    float4* __restrict__ out_ea,
    float4* __restrict__ out_norm) {
    int k = blockIdx.x;
    int d4 = threadIdx.x & 63;      // float4 column 0..63
    int ph = threadIdx.x >> 6;      // row phase 0..3

    int start = g_offsets[k];
    int end   = g_offsets[k + 1];

    float4 a0 = make_float4(0.f, 0.f, 0.f, 0.f);
    float4 a1 = make_float4(0.f, 0.f, 0.f, 0.f);
    float4 a2 = make_float4(0.f, 0.f, 0.f, 0.f);
    float4 a3 = make_float4(0.f, 0.f, 0.f, 0.f);

    int j = start + ph;
    // 4 independent in-flight float4 loads per thread
    for (; j + 12 < end; j += 16) {
        int r0 = g_order[j];
        int r1 = g_order[j + 4];
        int r2 = g_order[j + 8];
        int r3 = g_order[j + 12];
        float4 v0 = __ldg(enc + (size_t)r0 * 64 + d4);
        float4 v1 = __ldg(enc + (size_t)r1 * 64 + d4);
        float4 v2 = __ldg(enc + (size_t)r2 * 64 + d4);
        float4 v3 = __ldg(enc + (size_t)r3 * 64 + d4);
        a0.x += v0.x; a0.y += v0.y; a0.z += v0.z; a0.w += v0.w;
        a1.x += v1.x; a1.y += v1.y; a1.z += v1.z; a1.w += v1.w;
        a2.x += v2.x; a2.y += v2.y; a2.z += v2.z; a2.w += v2.w;
        a3.x += v3.x; a3.y += v3.y; a3.z += v3.z; a3.w += v3.w;
    }
    for (; j < end; j += 4) {
        int r = g_order[j];
        float4 v = __ldg(enc + (size_t)r * 64 + d4);
        a0.x += v.x; a0.y += v.y; a0.z += v.z; a0.w += v.w;
    }
    a0.x += a1.x + a2.x + a3.x;
    a0.y += a1.y + a2.y + a3.y;
    a0.z += a1.z + a2.z + a3.z;
    a0.w += a1.w + a2.w + a3.w;

    __shared__ float4 sh[256];
    sh[threadIdx.x] = a0;
    __syncthreads();

    if (ph == 0) {
        float4 s0 = sh[d4];
        float4 s1 = sh[d4 + 64];
        float4 s2 = sh[d4 + 128];
        float4 s3 = sh[d4 + 192];
        float4 acc;
        acc.x = (s0.x + s1.x) + (s2.x + s3.x);
        acc.y = (s0.y + s1.y) + (s2.y + s3.y);
        acc.z = (s0.z + s1.z) + (s2.z + s3.z);
        acc.w = (s0.w + s1.w) + (s2.w + s3.w);

        size_t o = (size_t)k * 64 + d4;
        float4 ea = embed_avg[o];
        float4 nea;
        nea.x = ea.x * DECAY + ONE_MINUS_DECAY * acc.x;
        nea.y = ea.y * DECAY + ONE_MINUS_DECAY * acc.y;
        nea.z = ea.z * DECAY + ONE_MINUS_DECAY * acc.z;
        nea.w = ea.w * DECAY + ONE_MINUS_DECAY * acc.w;
        out_ea[o] = nea;
        float inv = g_inv_smoothed[k];
        float4 nrm;
        nrm.x = nea.x * inv; nrm.y = nea.y * inv;
        nrm.z = nea.z * inv; nrm.w = nea.w * inv;
        out_norm[o] = nrm;
    }
}

// ---------------------------------------------------------------------------
// Launch
// Inputs (metadata order): indices[int32 N], encodings[f32 N*D],
//                          cluster_size[f32 K], embed_avg[f32 K*D]
// Output: concat(new_cs[K], new_ea[K*D], embed_normalized[K*D])
// ---------------------------------------------------------------------------
extern "C" void kernel_launch(void* const* d_in, const int* in_sizes, int n_in,
                              void* d_out, int out_size) {
    const int*   indices      = (const int*)d_in[0];
    const float* encodings    = (const float*)d_in[1];
    const float* cluster_size = (const float*)d_in[2];
    const float* embed_avg    = (const float*)d_in[3];

    float* out_cs   = (float*)d_out;                 // [K]
    float* out_ea   = out_cs + KK;                   // [K, D]
    float* out_norm = out_ea + (size_t)KK * DD;      // [K, D]

    k_blockhist<<<NB, CHUNK>>>(indices);
    k_scan_blocks<<<KK, NB>>>();
    k_scan_cs<<<1, KK>>>(cluster_size, out_cs);
    k_scatter<<<NB, CHUNK>>>(indices);
    k_reduce<<<KK, 256>>>((const float4*)encodings, (const float4*)embed_avg,
                          (float4*)out_ea, (float4*)out_norm);
}

// round 3
// speedup vs baseline: 1.2800x; 1.0145x over previous
#include <cuda_runtime.h>
#include <cuda_bf16.h>

// Problem constants (match reference_code)
#define NN 262144
#define KK 1024
#define DD 256
#define NB 64                 // partitions (hist/scatter blocks)
#define CHUNK 4096            // indices per partition (NN / NB)
#define ITEMS 4               // CHUNK / 1024 threads
#define DECAY 0.99f
#define ONE_MINUS_DECAY 0.01f
#define EPS 1e-5f

// Scratch (device globals; no allocation allowed)
__device__ int   g_bh[NB * KK];       // [b][k] hist -> exclusive prefix over b
__device__ int   g_ktotal[KK];        // per-code total count
__device__ int   g_offsets[KK + 1];   // exclusive scan over codes
__device__ int   g_order[NN];         // row ids grouped by code
__device__ float g_inv_smoothed[KK];

// ---------------------------------------------------------------------------
// Kernel 1: per-partition histogram (smem atomics), coalesced b-major write.
// ---------------------------------------------------------------------------
__global__ void __launch_bounds__(1024) k_blockhist(const int* __restrict__ idx) {
    __shared__ int h[KK];
    int t = threadIdx.x;
    int b = blockIdx.x;
    h[t] = 0;
    __syncthreads();
    #pragma unroll
    for (int it = 0; it < ITEMS; ++it) {
        int k = idx[b * CHUNK + it * 1024 + t];
        atomicAdd(&h[k], 1);
    }
    __syncthreads();
    g_bh[b * KK + t] = h[t];           // contiguous 4KB per block
}

// ---------------------------------------------------------------------------
// Kernel 2a: tiled transpose-scan. 32 CTAs, each owns 32 codes.
// Load [NB=64 rows x 32 codes] tile coalesced, warp-per-code scan along b,
// coalesced writeback of exclusive prefixes; totals -> g_ktotal.
// ---------------------------------------------------------------------------
__global__ void __launch_bounds__(1024) k_scan_blocks() {
    __shared__ int s[NB][33];          // padded: scan access stride 33 -> conflict-free
    int t = threadIdx.x;
    int lane = t & 31, warp = t >> 5;  // warp 0..31
    int k0 = blockIdx.x * 32;

    // coalesced load: thread (row=warp, col=lane) covers rows warp and warp+32
    s[warp][lane]      = g_bh[warp * KK + k0 + lane];
    s[warp + 32][lane] = g_bh[(warp + 32) * KK + k0 + lane];
    __syncthreads();

    // warp w scans code k0+w along b (64 values = 2 shuffle-scan segments)
    {
        int w = warp;
        int v0 = s[lane][w];
        int i0 = v0;
        #pragma unroll
        for (int o = 1; o < 32; o <<= 1) {
            int x = __shfl_up_sync(0xffffffffu, i0, o);
            if (lane >= o) i0 += x;
        }
        int carry = __shfl_sync(0xffffffffu, i0, 31);
        int v1 = s[lane + 32][w];
        int i1 = v1;
        #pragma unroll
        for (int o = 1; o < 32; o <<= 1) {
            int x = __shfl_up_sync(0xffffffffu, i1, o);
            if (lane >= o) i1 += x;
        }
        s[lane][w]      = i0 - v0;             // exclusive
        s[lane + 32][w] = carry + i1 - v1;
        if (lane == 31) g_ktotal[k0 + w] = carry + i1;
    }
    __syncthreads();

    g_bh[warp * KK + k0 + lane]        = s[warp][lane];
    g_bh[(warp + 32) * KK + k0 + lane] = s[warp + 32][lane];
}

// ---------------------------------------------------------------------------
// Kernel 2b: single block, 1024 threads.
//  - exclusive scan of g_ktotal -> g_offsets
//  - new_cs -> out_cs ; n = sum(new_cs) ; g_inv_smoothed
// ---------------------------------------------------------------------------
__global__ void __launch_bounds__(KK) k_scan_cs(const float* __restrict__ cluster_size,
                                                float* __restrict__ out_cs) {
    int t = threadIdx.x;
    int lane = t & 31, warp = t >> 5;

    int c = g_ktotal[t];

    int incl = c;
    #pragma unroll
    for (int o = 1; o < 32; o <<= 1) {
        int x = __shfl_up_sync(0xffffffffu, incl, o);
        if (lane >= o) incl += x;
    }
    __shared__ int wsum[32];
    if (lane == 31) wsum[warp] = incl;
    __syncthreads();
    if (warp == 0) {
        int s = wsum[lane];
        int si = s;
        #pragma unroll
        for (int o = 1; o < 32; o <<= 1) {
            int x = __shfl_up_sync(0xffffffffu, si, o);
            if (lane >= o) si += x;
        }
        wsum[lane] = si - s;
    }
    __syncthreads();
    int excl = incl - c + wsum[warp];

    g_offsets[t] = excl;
    if (t == KK - 1) g_offsets[KK] = excl + c;

    float ncs = cluster_size[t] * DECAY + ONE_MINUS_DECAY * (float)c;
    out_cs[t] = ncs;

    float v = ncs;
    #pragma unroll
    for (int o = 16; o > 0; o >>= 1)
        v += __shfl_down_sync(0xffffffffu, v, o);
    __shared__ float wred[32];
    if (lane == 0) wred[warp] = v;
    __syncthreads();
    __shared__ float n_sh;
    if (warp == 0) {
        float s = wred[lane];
        #pragma unroll
        for (int o = 16; o > 0; o >>= 1)
            s += __shfl_down_sync(0xffffffffu, s, o);
        if (lane == 0) n_sh = s;
    }
    __syncthreads();
    float n = n_sh;

    float smoothed = (ncs + EPS) / (n + (float)KK * EPS) * n;
    g_inv_smoothed[t] = 1.0f / smoothed;
}

// ---------------------------------------------------------------------------
// Kernel 3: scatter — smem cursors preloaded with global base (coalesced),
// rank via smem atomics, positions written directly. No global atomics.
// ---------------------------------------------------------------------------
__global__ void __launch_bounds__(1024) k_scatter(const int* __restrict__ idx) {
    __shared__ int cur[KK];
    int t = threadIdx.x;
    int b = blockIdx.x;
    cur[t] = g_offsets[t] + g_bh[b * KK + t];   // both coalesced 4KB reads
    __syncthreads();
    #pragma unroll
    for (int it = 0; it < ITEMS; ++it) {
        int i = b * CHUNK + it * 1024 + t;
        int k = idx[i];
        int pos = atomicAdd(&cur[k], 1);
        g_order[pos] = i;
    }
}

// ---------------------------------------------------------------------------
// Kernel 4: per-code gather-reduce (float4) + fused EMA epilogue.
// ---------------------------------------------------------------------------
__global__ void __launch_bounds__(256) k_reduce(
    const float4* __restrict__ enc,        // [N, 64] float4
    const float4* __restrict__ embed_avg,  // [K, 64] float4
    float4* __restrict__ out_ea,
    float4* __restrict__ out_norm) {
    int k = blockIdx.x;
    int d4 = threadIdx.x & 63;      // float4 column 0..63
    int ph = threadIdx.x >> 6;      // row phase 0..3

    int start = g_offsets[k];
    int end   = g_offsets[k + 1];

    float4 a0 = make_float4(0.f, 0.f, 0.f, 0.f);
    float4 a1 = make_float4(0.f, 0.f, 0.f, 0.f);
    float4 a2 = make_float4(0.f, 0.f, 0.f, 0.f);
    float4 a3 = make_float4(0.f, 0.f, 0.f, 0.f);

    int j = start + ph;
    for (; j + 12 < end; j += 16) {
        int r0 = g_order[j];
        int r1 = g_order[j + 4];
        int r2 = g_order[j + 8];
        int r3 = g_order[j + 12];
        float4 v0 = __ldg(enc + (size_t)r0 * 64 + d4);
        float4 v1 = __ldg(enc + (size_t)r1 * 64 + d4);
        float4 v2 = __ldg(enc + (size_t)r2 * 64 + d4);
        float4 v3 = __ldg(enc + (size_t)r3 * 64 + d4);
        a0.x += v0.x; a0.y += v0.y; a0.z += v0.z; a0.w += v0.w;
        a1.x += v1.x; a1.y += v1.y; a1.z += v1.z; a1.w += v1.w;
        a2.x += v2.x; a2.y += v2.y; a2.z += v2.z; a2.w += v2.w;
        a3.x += v3.x; a3.y += v3.y; a3.z += v3.z; a3.w += v3.w;
    }
    for (; j < end; j += 4) {
        int r = g_order[j];
        float4 v = __ldg(enc + (size_t)r * 64 + d4);
        a0.x += v.x; a0.y += v.y; a0.z += v.z; a0.w += v.w;
    }
    a0.x += a1.x + a2.x + a3.x;
    a0.y += a1.y + a2.y + a3.y;
    a0.z += a1.z + a2.z + a3.z;
    a0.w += a1.w + a2.w + a3.w;

    __shared__ float4 sh[256];
    sh[threadIdx.x] = a0;
    __syncthreads();

    if (ph == 0) {
        float4 s0 = sh[d4];
        float4 s1 = sh[d4 + 64];
        float4 s2 = sh[d4 + 128];
        float4 s3 = sh[d4 + 192];
        float4 acc;
        acc.x = (s0.x + s1.x) + (s2.x + s3.x);
        acc.y = (s0.y + s1.y) + (s2.y + s3.y);
        acc.z = (s0.z + s1.z) + (s2.z + s3.z);
        acc.w = (s0.w + s1.w) + (s2.w + s3.w);

        size_t o = (size_t)k * 64 + d4;
        float4 ea = embed_avg[o];
        float4 nea;
        nea.x = ea.x * DECAY + ONE_MINUS_DECAY * acc.x;
        nea.y = ea.y * DECAY + ONE_MINUS_DECAY * acc.y;
        nea.z = ea.z * DECAY + ONE_MINUS_DECAY * acc.z;
        nea.w = ea.w * DECAY + ONE_MINUS_DECAY * acc.w;
        out_ea[o] = nea;
        float inv = g_inv_smoothed[k];
        float4 nrm;
        nrm.x = nea.x * inv; nrm.y = nea.y * inv;
        nrm.z = nea.z * inv; nrm.w = nea.w * inv;
        out_norm[o] = nrm;
    }
}

// ---------------------------------------------------------------------------
// Launch
// Inputs (metadata order): indices[int32 N], encodings[f32 N*D],
//                          cluster_size[f32 K], embed_avg[f32 K*D]
// Output: concat(new_cs[K], new_ea[K*D], embed_normalized[K*D])
// ---------------------------------------------------------------------------
extern "C" void kernel_launch(void* const* d_in, const int* in_sizes, int n_in,
                              void* d_out, int out_size) {
    const int*   indices      = (const int*)d_in[0];
    const float* encodings    = (const float*)d_in[1];
    const float* cluster_size = (const float*)d_in[2];
    const float* embed_avg    = (const float*)d_in[3];

    float* out_cs   = (float*)d_out;                 // [K]
    float* out_ea   = out_cs + KK;                   // [K, D]
    float* out_norm = out_ea + (size_t)KK * DD;      // [K, D]

    k_blockhist<<<NB, 1024>>>(indices);
    k_scan_blocks<<<KK / 32, 1024>>>();
    k_scan_cs<<<1, KK>>>(cluster_size, out_cs);
    k_scatter<<<NB, 1024>>>(indices);
    k_reduce<<<KK, 256>>>((const float4*)encodings, (const float4*)embed_avg,
                          (float4*)out_ea, (float4*)out_norm);
}

// round 4
// speedup vs baseline: 1.2806x; 1.0005x over previous
#include <cuda_runtime.h>
#include <cuda_bf16.h>

// Problem constants (match reference_code)
#define NN 262144
#define KK 1024
#define DD 256
#define NB 128                // partitions (hist/scatter blocks)
#define CHUNK 2048            // indices per partition (NN / NB)
#define DECAY 0.99f
#define ONE_MINUS_DECAY 0.01f
#define EPS 1e-5f

// Scratch (device globals; no allocation allowed)
__device__ int   g_bh[NB * KK];       // [b][k] hist -> exclusive prefix over b
__device__ int   g_ktotal[KK];        // per-code total count
__device__ int   g_offsets[KK + 1];   // exclusive scan over codes
__device__ int   g_order[NN];         // row ids grouped by code
__device__ float g_inv_smoothed[KK];

// ---------------------------------------------------------------------------
// Kernel 1: per-partition histogram (smem atomics), coalesced b-major write.
// 128 CTAs for chip coverage.
// ---------------------------------------------------------------------------
__global__ void __launch_bounds__(1024) k_blockhist(const int* __restrict__ idx) {
    __shared__ int h[KK];
    int t = threadIdx.x;
    int b = blockIdx.x;
    h[t] = 0;
    __syncthreads();
    int base = b * CHUNK;
    int k0 = idx[base + t];
    int k1 = idx[base + 1024 + t];
    atomicAdd(&h[k0], 1);
    atomicAdd(&h[k1], 1);
    __syncthreads();
    g_bh[b * KK + t] = h[t];           // contiguous 4KB per block
}

// ---------------------------------------------------------------------------
// Kernel 2a: tiled transpose-scan. 32 CTAs, each owns 32 codes.
// Load [NB=128 rows x 32 codes] tile coalesced, warp-per-code scan along b
// (4 shuffle segments with carry), coalesced writeback; totals -> g_ktotal.
// ---------------------------------------------------------------------------
__global__ void __launch_bounds__(1024) k_scan_blocks() {
    __shared__ int s[NB][33];          // padded -> conflict-free column access
    int t = threadIdx.x;
    int lane = t & 31, warp = t >> 5;  // warp 0..31
    int k0 = blockIdx.x * 32;

    // coalesced load: 4096 ints, thread covers 4 rows at its lane column
    #pragma unroll
    for (int r = 0; r < 4; ++r) {
        int row = r * 32 + warp;
        s[row][lane] = g_bh[row * KK + k0 + lane];
    }
    __syncthreads();

    // warp w scans code k0+w along the 128 blocks (4 segments of 32)
    {
        int w = warp;
        int carry = 0;
        #pragma unroll
        for (int seg = 0; seg < 4; ++seg) {
            int v = s[seg * 32 + lane][w];
            int incl = v;
            #pragma unroll
            for (int o = 1; o < 32; o <<= 1) {
                int x = __shfl_up_sync(0xffffffffu, incl, o);
                if (lane >= o) incl += x;
            }
            s[seg * 32 + lane][w] = carry + incl - v;   // exclusive
            carry += __shfl_sync(0xffffffffu, incl, 31);
        }
        if (lane == 0) g_ktotal[k0 + w] = carry;
    }
    __syncthreads();

    #pragma unroll
    for (int r = 0; r < 4; ++r) {
        int row = r * 32 + warp;
        g_bh[row * KK + k0 + lane] = s[row][lane];
    }
}

// ---------------------------------------------------------------------------
// Kernel 2b: single block, 1024 threads.
//  - exclusive scan of g_ktotal -> g_offsets
//  - new_cs -> out_cs ; n = sum(new_cs) ; g_inv_smoothed
// ---------------------------------------------------------------------------
__global__ void __launch_bounds__(KK) k_scan_cs(const float* __restrict__ cluster_size,
                                                float* __restrict__ out_cs) {
    int t = threadIdx.x;
    int lane = t & 31, warp = t >> 5;

    int c = g_ktotal[t];

    int incl = c;
    #pragma unroll
    for (int o = 1; o < 32; o <<= 1) {
        int x = __shfl_up_sync(0xffffffffu, incl, o);
        if (lane >= o) incl += x;
    }
    __shared__ int wsum[32];
    if (lane == 31) wsum[warp] = incl;
    __syncthreads();
    if (warp == 0) {
        int s = wsum[lane];
        int si = s;
        #pragma unroll
        for (int o = 1; o < 32; o <<= 1) {
            int x = __shfl_up_sync(0xffffffffu, si, o);
            if (lane >= o) si += x;
        }
        wsum[lane] = si - s;
    }
    __syncthreads();
    int excl = incl - c + wsum[warp];

    g_offsets[t] = excl;
    if (t == KK - 1) g_offsets[KK] = excl + c;

    float ncs = cluster_size[t] * DECAY + ONE_MINUS_DECAY * (float)c;
    out_cs[t] = ncs;

    float v = ncs;
    #pragma unroll
    for (int o = 16; o > 0; o >>= 1)
        v += __shfl_down_sync(0xffffffffu, v, o);
    __shared__ float wred[32];
    if (lane == 0) wred[warp] = v;
    __syncthreads();
    __shared__ float n_sh;
    if (warp == 0) {
        float s = wred[lane];
        #pragma unroll
        for (int o = 16; o > 0; o >>= 1)
            s += __shfl_down_sync(0xffffffffu, s, o);
        if (lane == 0) n_sh = s;
    }
    __syncthreads();
    float n = n_sh;

    float smoothed = (ncs + EPS) / (n + (float)KK * EPS) * n;
    g_inv_smoothed[t] = 1.0f / smoothed;
}

// ---------------------------------------------------------------------------
// Kernel 3: scatter — smem cursors preloaded with global base (coalesced),
// rank via smem atomics, positions written directly. No global atomics.
// ---------------------------------------------------------------------------
__global__ void __launch_bounds__(1024) k_scatter(const int* __restrict__ idx) {
    __shared__ int cur[KK];
    int t = threadIdx.x;
    int b = blockIdx.x;
    cur[t] = g_offsets[t] + g_bh[b * KK + t];   // both coalesced 4KB reads
    __syncthreads();
    int base = b * CHUNK;
    int i0 = base + t;
    int i1 = base + 1024 + t;
    int k0 = idx[i0];
    int k1 = idx[i1];
    int p0 = atomicAdd(&cur[k0], 1);
    g_order[p0] = i0;
    int p1 = atomicAdd(&cur[k1], 1);
    g_order[p1] = i1;
}

// ---------------------------------------------------------------------------
// Kernel 4: per-code gather-reduce (float4) + fused EMA epilogue.
// ---------------------------------------------------------------------------
__global__ void __launch_bounds__(256) k_reduce(
    const float4* __restrict__ enc,        // [N, 64] float4
    const float4* __restrict__ embed_avg,  // [K, 64] float4
    float4* __restrict__ out_ea,
    float4* __restrict__ out_norm) {
    int k = blockIdx.x;
    int d4 = threadIdx.x & 63;      // float4 column 0..63
    int ph = threadIdx.x >> 6;      // row phase 0..3

    int start = g_offsets[k];
    int end   = g_offsets[k + 1];

    float4 a0 = make_float4(0.f, 0.f, 0.f, 0.f);
    float4 a1 = make_float4(0.f, 0.f, 0.f, 0.f);
    float4 a2 = make_float4(0.f, 0.f, 0.f, 0.f);
    float4 a3 = make_float4(0.f, 0.f, 0.f, 0.f);

    int j = start + ph;
    for (; j + 12 < end; j += 16) {
        int r0 = g_order[j];
        int r1 = g_order[j + 4];
        int r2 = g_order[j + 8];
        int r3 = g_order[j + 12];
        float4 v0 = __ldg(enc + (size_t)r0 * 64 + d4);
        float4 v1 = __ldg(enc + (size_t)r1 * 64 + d4);
        float4 v2 = __ldg(enc + (size_t)r2 * 64 + d4);
        float4 v3 = __ldg(enc + (size_t)r3 * 64 + d4);
        a0.x += v0.x; a0.y += v0.y; a0.z += v0.z; a0.w += v0.w;
        a1.x += v1.x; a1.y += v1.y; a1.z += v1.z; a1.w += v1.w;
        a2.x += v2.x; a2.y += v2.y; a2.z += v2.z; a2.w += v2.w;
        a3.x += v3.x; a3.y += v3.y; a3.z += v3.z; a3.w += v3.w;
    }
    for (; j < end; j += 4) {
        int r = g_order[j];
        float4 v = __ldg(enc + (size_t)r * 64 + d4);
        a0.x += v.x; a0.y += v.y; a0.z += v.z; a0.w += v.w;
    }
    a0.x += a1.x + a2.x + a3.x;
    a0.y += a1.y + a2.y + a3.y;
    a0.z += a1.z + a2.z + a3.z;
    a0.w += a1.w + a2.w + a3.w;

    __shared__ float4 sh[256];
    sh[threadIdx.x] = a0;
    __syncthreads();

    if (ph == 0) {
        float4 s0 = sh[d4];
        float4 s1 = sh[d4 + 64];
        float4 s2 = sh[d4 + 128];
        float4 s3 = sh[d4 + 192];
        float4 acc;
        acc.x = (s0.x + s1.x) + (s2.x + s3.x);
        acc.y = (s0.y + s1.y) + (s2.y + s3.y);
        acc.z = (s0.z + s1.z) + (s2.z + s3.z);
        acc.w = (s0.w + s1.w) + (s2.w + s3.w);

        size_t o = (size_t)k * 64 + d4;
        float4 ea = embed_avg[o];
        float4 nea;
        nea.x = ea.x * DECAY + ONE_MINUS_DECAY * acc.x;
        nea.y = ea.y * DECAY + ONE_MINUS_DECAY * acc.y;
        nea.z = ea.z * DECAY + ONE_MINUS_DECAY * acc.z;
        nea.w = ea.w * DECAY + ONE_MINUS_DECAY * acc.w;
        out_ea[o] = nea;
        float inv = g_inv_smoothed[k];
        float4 nrm;
        nrm.x = nea.x * inv; nrm.y = nea.y * inv;
        nrm.z = nea.z * inv; nrm.w = nea.w * inv;
        out_norm[o] = nrm;
    }
}

// ---------------------------------------------------------------------------
// Launch
// Inputs (metadata order): indices[int32 N], encodings[f32 N*D],
//                          cluster_size[f32 K], embed_avg[f32 K*D]
// Output: concat(new_cs[K], new_ea[K*D], embed_normalized[K*D])
// ---------------------------------------------------------------------------
extern "C" void kernel_launch(void* const* d_in, const int* in_sizes, int n_in,
                              void* d_out, int out_size) {
    const int*   indices      = (const int*)d_in[0];
    const float* encodings    = (const float*)d_in[1];
    const float* cluster_size = (const float*)d_in[2];
    const float* embed_avg    = (const float*)d_in[3];

    float* out_cs   = (float*)d_out;                 // [K]
    float* out_ea   = out_cs + KK;                   // [K, D]
    float* out_norm = out_ea + (size_t)KK * DD;      // [K, D]

    k_blockhist<<<NB, 1024>>>(indices);
    k_scan_blocks<<<KK / 32, 1024>>>();
    k_scan_cs<<<1, KK>>>(cluster_size, out_cs);
    k_scatter<<<NB, 1024>>>(indices);
    k_reduce<<<KK, 256>>>((const float4*)encodings, (const float4*)embed_avg,
                          (float4*)out_ea, (float4*)out_norm);
}

// round 5
// speedup vs baseline: 1.3947x; 1.0892x over previous
#include <cuda_runtime.h>
#include <cuda_bf16.h>

// Problem constants (match reference_code)
#define NN 262144
#define KK 1024
#define DD 256
#define NBLK 128              // fused-prologue CTAs (all co-resident)
#define CHUNK 2048            // indices per CTA (NN / NBLK)
#define DECAY 0.99f
#define ONE_MINUS_DECAY 0.01f
#define EPS 1e-5f

// Scratch (device globals; no allocation allowed)
__device__ int      g_bh[NBLK * KK];     // [b][k] hist -> exclusive prefix over b
__device__ int      g_ktotal[KK];        // per-code total count
__device__ int      g_offsets[KK + 1];   // exclusive scan over codes
__device__ int      g_order[NN];         // row ids grouped by code
__device__ float    g_inv_smoothed[KK];
__device__ unsigned g_bar_cnt[4];        // software grid barrier state
__device__ unsigned g_bar_gen[4];        // (zero-init; replay-safe: gen monotone)

// ---------------------------------------------------------------------------
// Software grid barrier (all NBLK CTAs co-resident by construction).
// Distinct id per call site; cnt self-resets before gen bump, so state is
// clean for the next graph replay.
// ---------------------------------------------------------------------------
__device__ __forceinline__ void grid_barrier(int id) {
    __syncthreads();
    if (threadIdx.x == 0) {
        volatile unsigned* genp = &g_bar_gen[id];
        unsigned gen = *genp;
        __threadfence();
        unsigned arrived = atomicAdd(&g_bar_cnt[id], 1u);
        if (arrived == (unsigned)(NBLK - 1)) {
            g_bar_cnt[id] = 0u;
            __threadfence();
            *genp = gen + 1u;
        } else {
            while (*genp == gen) { __nanosleep(64); }
        }
        __threadfence();
    }
    __syncthreads();
}

// ---------------------------------------------------------------------------
// Fused prologue: hist -> transpose scan -> code scan/cs epilogue -> scatter.
// Indices are read ONCE into registers and reused for the scatter phase.
// ---------------------------------------------------------------------------
__global__ void __launch_bounds__(1024) k_prologue(
    const int* __restrict__ idx,
    const float* __restrict__ cluster_size,
    float* __restrict__ out_cs) {
    __shared__ union {
        int h[KK];            // phase A: histogram / phase D: cursors
        int s[NBLK][33];      // phase B: transpose-scan tile (padded)
        struct { int wsum[32]; float wred[32]; float n_sh; } cs;  // phase C
    } sm;

    int t = threadIdx.x;
    int b = blockIdx.x;
    int lane = t & 31, warp = t >> 5;

    // ---- Phase A: per-CTA histogram (indices -> registers) ----
    sm.h[t] = 0;
    __syncthreads();
    int base = b * CHUNK;
    int k0 = idx[base + t];
    int k1 = idx[base + 1024 + t];
    atomicAdd(&sm.h[k0], 1);
    atomicAdd(&sm.h[k1], 1);
    __syncthreads();
    g_bh[b * KK + t] = sm.h[t];               // contiguous 4KB per CTA

    grid_barrier(0);

    // ---- Phase B: CTAs 0..31 transpose-scan g_bh along b for 32 codes each ----
    if (b < 32) {
        int c0 = b * 32;
        #pragma unroll
        for (int r = 0; r < 4; ++r) {
            int row = r * 32 + warp;
            sm.s[row][lane] = g_bh[row * KK + c0 + lane];
        }
        __syncthreads();
        {
            int w = warp;
            int carry = 0;
            #pragma unroll
            for (int seg = 0; seg < 4; ++seg) {
                int v = sm.s[seg * 32 + lane][w];
                int incl = v;
                #pragma unroll
                for (int o = 1; o < 32; o <<= 1) {
                    int x = __shfl_up_sync(0xffffffffu, incl, o);
                    if (lane >= o) incl += x;
                }
                sm.s[seg * 32 + lane][w] = carry + incl - v;   // exclusive
                carry += __shfl_sync(0xffffffffu, incl, 31);
            }
            if (lane == 0) g_ktotal[c0 + w] = carry;
        }
        __syncthreads();
        #pragma unroll
        for (int r = 0; r < 4; ++r) {
            int row = r * 32 + warp;
            g_bh[row * KK + c0 + lane] = sm.s[row][lane];
        }
    }

    grid_barrier(1);

    // ---- Phase C: CTA 32 scans code totals + cs epilogue ----
    if (b == 32) {
        int c = g_ktotal[t];
        int incl = c;
        #pragma unroll
        for (int o = 1; o < 32; o <<= 1) {
            int x = __shfl_up_sync(0xffffffffu, incl, o);
            if (lane >= o) incl += x;
        }
        if (lane == 31) sm.cs.wsum[warp] = incl;
        __syncthreads();
        if (warp == 0) {
            int s = sm.cs.wsum[lane];
            int si = s;
            #pragma unroll
            for (int o = 1; o < 32; o <<= 1) {
                int x = __shfl_up_sync(0xffffffffu, si, o);
                if (lane >= o) si += x;
            }
            sm.cs.wsum[lane] = si - s;
        }
        __syncthreads();
        int excl = incl - c + sm.cs.wsum[warp];

        g_offsets[t] = excl;
        if (t == KK - 1) g_offsets[KK] = excl + c;

        float ncs = cluster_size[t] * DECAY + ONE_MINUS_DECAY * (float)c;
        out_cs[t] = ncs;

        float v = ncs;
        #pragma unroll
        for (int o = 16; o > 0; o >>= 1)
            v += __shfl_down_sync(0xffffffffu, v, o);
        if (lane == 0) sm.cs.wred[warp] = v;
        __syncthreads();
        if (warp == 0) {
            float s = sm.cs.wred[lane];
            #pragma unroll
            for (int o = 16; o > 0; o >>= 1)
                s += __shfl_down_sync(0xffffffffu, s, o);
            if (lane == 0) sm.cs.n_sh = s;
        }
        __syncthreads();
        float n = sm.cs.n_sh;

        float smoothed = (ncs + EPS) / (n + (float)KK * EPS) * n;
        g_inv_smoothed[t] = 1.0f / smoothed;
    }

    grid_barrier(2);

    // ---- Phase D: scatter with register-held indices ----
    sm.h[t] = g_offsets[t] + g_bh[b * KK + t];   // coalesced, L2-hot
    __syncthreads();
    int p0 = atomicAdd(&sm.h[k0], 1);
    g_order[p0] = base + t;
    int p1 = atomicAdd(&sm.h[k1], 1);
    g_order[p1] = base + 1024 + t;
}

// ---------------------------------------------------------------------------
// Reduce: per-code gather-reduce (float4) + fused EMA epilogue.
// g_order is staged through smem in 1024-row tiles so enc loads are
// address-independent streams (no LDG->LDG dependent chain).
// ---------------------------------------------------------------------------
__global__ void __launch_bounds__(256) k_reduce(
    const float4* __restrict__ enc,        // [N, 64] float4
    const float4* __restrict__ embed_avg,  // [K, 64] float4
    float4* __restrict__ out_ea,
    float4* __restrict__ out_norm) {
    __shared__ int ord[1024];
    __shared__ float4 sh[256];

    int k = blockIdx.x;
    int d4 = threadIdx.x & 63;      // float4 column 0..63
    int ph = threadIdx.x >> 6;      // row phase 0..3

    int start = g_offsets[k];
    int cnt   = g_offsets[k + 1] - start;

    float4 a0 = make_float4(0.f, 0.f, 0.f, 0.f);
    float4 a1 = make_float4(0.f, 0.f, 0.f, 0.f);
    float4 a2 = make_float4(0.f, 0.f, 0.f, 0.f);
    float4 a3 = make_float4(0.f, 0.f, 0.f, 0.f);

    for (int t0 = 0; t0 < cnt; t0 += 1024) {
        int tile = min(1024, cnt - t0);
        __syncthreads();
        for (int i = threadIdx.x; i < tile; i += 256)
            ord[i] = g_order[start + t0 + i];
        __syncthreads();

        int j = ph;
        for (; j + 12 < tile; j += 16) {
            int r0 = ord[j];
            int r1 = ord[j + 4];
            int r2 = ord[j + 8];
            int r3 = ord[j + 12];
            float4 v0 = __ldg(enc + (size_t)r0 * 64 + d4);
            float4 v1 = __ldg(enc + (size_t)r1 * 64 + d4);
            float4 v2 = __ldg(enc + (size_t)r2 * 64 + d4);
            float4 v3 = __ldg(enc + (size_t)r3 * 64 + d4);
            a0.x += v0.x; a0.y += v0.y; a0.z += v0.z; a0.w += v0.w;
            a1.x += v1.x; a1.y += v1.y; a1.z += v1.z; a1.w += v1.w;
            a2.x += v2.x; a2.y += v2.y; a2.z += v2.z; a2.w += v2.w;
            a3.x += v3.x; a3.y += v3.y; a3.z += v3.z; a3.w += v3.w;
        }
        for (; j < tile; j += 4) {
            int r = ord[j];
            float4 v = __ldg(enc + (size_t)r * 64 + d4);
            a0.x += v.x; a0.y += v.y; a0.z += v.z; a0.w += v.w;
        }
    }

    a0.x += a1.x + a2.x + a3.x;
    a0.y += a1.y + a2.y + a3.y;
    a0.z += a1.z + a2.z + a3.z;
    a0.w += a1.w + a2.w + a3.w;

    __syncthreads();
    sh[threadIdx.x] = a0;
    __syncthreads();

    if (ph == 0) {
        float4 s0 = sh[d4];
        float4 s1 = sh[d4 + 64];
        float4 s2 = sh[d4 + 128];
        float4 s3 = sh[d4 + 192];
        float4 acc;
        acc.x = (s0.x + s1.x) + (s2.x + s3.x);
        acc.y = (s0.y + s1.y) + (s2.y + s3.y);
        acc.z = (s0.z + s1.z) + (s2.z + s3.z);
        acc.w = (s0.w + s1.w) + (s2.w + s3.w);

        size_t o = (size_t)k * 64 + d4;
        float4 ea = embed_avg[o];
        float4 nea;
        nea.x = ea.x * DECAY + ONE_MINUS_DECAY * acc.x;
        nea.y = ea.y * DECAY + ONE_MINUS_DECAY * acc.y;
        nea.z = ea.z * DECAY + ONE_MINUS_DECAY * acc.z;
        nea.w = ea.w * DECAY + ONE_MINUS_DECAY * acc.w;
        out_ea[o] = nea;
        float inv = g_inv_smoothed[k];
        float4 nrm;
        nrm.x = nea.x * inv; nrm.y = nea.y * inv;
        nrm.z = nea.z * inv; nrm.w = nea.w * inv;
        out_norm[o] = nrm;
    }
}

// ---------------------------------------------------------------------------
// Launch
// Inputs (metadata order): indices[int32 N], encodings[f32 N*D],
//                          cluster_size[f32 K], embed_avg[f32 K*D]
// Output: concat(new_cs[K], new_ea[K*D], embed_normalized[K*D])
// ---------------------------------------------------------------------------
extern "C" void kernel_launch(void* const* d_in, const int* in_sizes, int n_in,
                              void* d_out, int out_size) {
    const int*   indices      = (const int*)d_in[0];
    const float* encodings    = (const float*)d_in[1];
    const float* cluster_size = (const float*)d_in[2];
    const float* embed_avg    = (const float*)d_in[3];

    float* out_cs   = (float*)d_out;                 // [K]
    float* out_ea   = out_cs + KK;                   // [K, D]
    float* out_norm = out_ea + (size_t)KK * DD;      // [K, D]

    k_prologue<<<NBLK, 1024>>>(indices, cluster_size, out_cs);
    k_reduce<<<KK, 256>>>((const float4*)encodings, (const float4*)embed_avg,
                          (float4*)out_ea, (float4*)out_norm);
}